// round 4
// baseline (speedup 1.0000x reference)
#include <cuda_runtime.h>
#include <cstdint>

// Problem constants (fixed by the dataset)
#define BATCH 2
#define NPTS  16384
#define CH    64
#define SPTS  4096        // npoint
#define KNB   32          // nsample
#define R2    0.16f       // 0.4^2
#define OUTC  128

#define N_XYZ_OUT  (BATCH*SPTS*3)          // 24576
#define N_FEAT_OUT (BATCH*OUTC*SPTS)       // 1048576
#define OFF_FEAT   N_XYZ_OUT
#define OFF_SAMP   (N_XYZ_OUT + N_FEAT_OUT)

// Scratch (no allocation allowed -> device globals)
__device__ int g_idx[BATCH*SPTS*KNB];
__device__ __align__(16) float g_featT[(size_t)BATCH*NPTS*CH];

// ---------------------------------------------------------------------------
// Kernel 1: ball query. One warp per centroid, early exit at 32 hits.
// Replicates reference semantics: first `nsample` hits in index order,
// empty slots filled with first hit (0 if none).
// ---------------------------------------------------------------------------
__global__ void bq_kernel(const float* __restrict__ xyz) {
    int w    = (blockIdx.x * blockDim.x + threadIdx.x) >> 5;
    int lane = threadIdx.x & 31;
    if (w >= BATCH * SPTS) return;
    int b = w / SPTS, s = w % SPTS;
    const float* xb = xyz + (size_t)b * NPTS * 3;
    float qx = xb[s*3+0], qy = xb[s*3+1], qz = xb[s*3+2];
    float qq = qx*qx + qy*qy + qz*qz;
    int* idx = g_idx + (size_t)w * KNB;
    int cnt = 0;
    int firstIdx = 0;
    bool haveFirst = false;
    for (int j0 = 0; j0 < NPTS && cnt < KNB; j0 += 32) {
        int j = j0 + lane;
        float px = xb[j*3+0], py = xb[j*3+1], pz = xb[j*3+2];
        float pp  = px*px + py*py + pz*pz;
        float dot = qx*px + qy*py + qz*pz;
        float d2  = qq + pp - 2.0f*dot;   // same formula as reference
        bool hit = d2 < R2;
        unsigned mask = __ballot_sync(0xffffffffu, hit);
        if (mask && !haveFirst) {
            firstIdx = __shfl_sync(0xffffffffu, j, __ffs(mask) - 1);
            haveFirst = true;
        }
        int pos = cnt + __popc(mask & ((1u << lane) - 1u));
        if (hit && pos < KNB) idx[pos] = j;
        cnt += __popc(mask);
    }
    if (cnt < KNB && lane >= cnt) idx[lane] = firstIdx;
}

// ---------------------------------------------------------------------------
// Kernel 2: transpose features [B,C,N] -> [B,N,C] so neighbor gathers are
// contiguous 256B rows.
// ---------------------------------------------------------------------------
__global__ void transpose_kernel(const float* __restrict__ f) {
    __shared__ float tile[32][33];
    int b  = blockIdx.z;
    int c0 = blockIdx.y * 32;
    int n0 = blockIdx.x * 32;
    int tx = threadIdx.x, ty = threadIdx.y;
    const float* src = f + ((size_t)b * CH) * NPTS;
    #pragma unroll
    for (int r = ty; r < 32; r += 8)
        tile[r][tx] = src[(size_t)(c0 + r) * NPTS + n0 + tx];
    __syncthreads();
    float* dst = g_featT + ((size_t)b * NPTS) * CH;
    #pragma unroll
    for (int r = ty; r < 32; r += 8)
        dst[(size_t)(n0 + r) * CH + c0 + tx] = tile[tx][r];
}

// ---------------------------------------------------------------------------
// Kernel 3: trivial outputs (new_xyz copy, samp_idx as floats)
// ---------------------------------------------------------------------------
__global__ void misc_kernel(const float* __restrict__ xyz, float* __restrict__ out) {
    int i = blockIdx.x * blockDim.x + threadIdx.x;
    if (i < N_XYZ_OUT) {
        int b = i / (SPTS * 3), r = i % (SPTS * 3);
        out[i] = xyz[(size_t)b * NPTS * 3 + r];
    }
    if (i < BATCH * SPTS) {
        out[OFF_SAMP + i] = (float)(i % SPTS);
    }
}

// ---------------------------------------------------------------------------
// Kernel 4: gather + 3-layer MLP + maxpool. One 256-thread block handles one
// centroid at a time (grid-stride). Weights staged in smem once per block.
// smem activations use [c][k] layout padded to 33 for conflict-free access.
// ---------------------------------------------------------------------------
#define MLP_THREADS 256
// dynamic smem layout (floats)
#define OFF_W1  0                        // 67*64 = 4288
#define OFF_W2  (OFF_W1 + 67*64)         // +4096
#define OFF_W3  (OFF_W2 + 64*64)         // +8192
#define OFF_B1  (OFF_W3 + 64*128)
#define OFF_B2  (OFF_B1 + 64)
#define OFF_B3  (OFF_B2 + 64)
#define OFF_A   (OFF_B3 + 128)           // bufA: 68 rows * 33
#define OFF_BB  (OFF_A + 68*33)          // bufB: 64 rows * 33
#define SMEM_FLOATS (OFF_BB + 64*33)
#define SMEM_BYTES  (SMEM_FLOATS * 4)

__global__ void __launch_bounds__(MLP_THREADS, 2)
mlp_kernel(const float* __restrict__ xyz,
           const float* __restrict__ W1, const float* __restrict__ b1,
           const float* __restrict__ W2, const float* __restrict__ b2,
           const float* __restrict__ W3, const float* __restrict__ b3,
           float* __restrict__ out) {
    extern __shared__ float sm[];
    __shared__ int sidx[KNB];
    int t = threadIdx.x;
    // stage weights once
    for (int i = t; i < 67*64;  i += MLP_THREADS) sm[OFF_W1 + i] = W1[i];
    for (int i = t; i < 64*64;  i += MLP_THREADS) sm[OFF_W2 + i] = W2[i];
    for (int i = t; i < 64*128; i += MLP_THREADS) sm[OFF_W3 + i] = W3[i];
    if (t < 64)  sm[OFF_B1 + t] = b1[t];
    if (t < 64)  sm[OFF_B2 + t] = b2[t];
    if (t < 128) sm[OFF_B3 + t] = b3[t];
    __syncthreads();

    float* bufA = sm + OFF_A;
    float* bufB = sm + OFF_BB;
    int lane = t & 31;

    for (int cid = blockIdx.x; cid < BATCH * SPTS; cid += gridDim.x) {
        int b = cid / SPTS, s = cid % SPTS;
        if (t < KNB) sidx[t] = g_idx[(size_t)cid * KNB + t];
        __syncthreads();

        // ---- gather: g[c][k], c=0..2 rel-xyz, c=3..66 features ----
        {
            int k = t >> 3, j = t & 7;
            int n = sidx[k];
            const float4* fr = (const float4*)(g_featT + ((size_t)b * NPTS + n) * CH);
            float4 v0 = fr[j*2 + 0];
            float4 v1 = fr[j*2 + 1];
            int cb = 3 + j*8;
            bufA[(cb+0)*33 + k] = v0.x;
            bufA[(cb+1)*33 + k] = v0.y;
            bufA[(cb+2)*33 + k] = v0.z;
            bufA[(cb+3)*33 + k] = v0.w;
            bufA[(cb+4)*33 + k] = v1.x;
            bufA[(cb+5)*33 + k] = v1.y;
            bufA[(cb+6)*33 + k] = v1.z;
            bufA[(cb+7)*33 + k] = v1.w;
            if (t < KNB) {
                int n2 = sidx[t];
                const float* xb = xyz + (size_t)b * NPTS * 3;
                bufA[0*33 + t] = xb[n2*3+0] - xb[s*3+0];
                bufA[1*33 + t] = xb[n2*3+1] - xb[s*3+1];
                bufA[2*33 + t] = xb[n2*3+2] - xb[s*3+2];
            }
        }
        __syncthreads();

        // ---- layer 1: [32x67] @ [67x64] -> relu -> bufB ----
        {
            int k = t & 31, d0 = (t >> 5) * 8;
            float acc[8];
            #pragma unroll
            for (int i = 0; i < 8; i++) acc[i] = sm[OFF_B1 + d0 + i];
            #pragma unroll 4
            for (int c = 0; c < 67; c++) {
                float gv = bufA[c*33 + k];
                const float4* w4 = (const float4*)(sm + OFF_W1 + c*64 + d0);
                float4 w0 = w4[0], w1 = w4[1];
                acc[0] = fmaf(gv, w0.x, acc[0]);
                acc[1] = fmaf(gv, w0.y, acc[1]);
                acc[2] = fmaf(gv, w0.z, acc[2]);
                acc[3] = fmaf(gv, w0.w, acc[3]);
                acc[4] = fmaf(gv, w1.x, acc[4]);
                acc[5] = fmaf(gv, w1.y, acc[5]);
                acc[6] = fmaf(gv, w1.z, acc[6]);
                acc[7] = fmaf(gv, w1.w, acc[7]);
            }
            #pragma unroll
            for (int i = 0; i < 8; i++) bufB[(d0+i)*33 + k] = fmaxf(acc[i], 0.0f);
        }
        __syncthreads();

        // ---- layer 2: [32x64] @ [64x64] -> relu -> bufA ----
        {
            int k = t & 31, d0 = (t >> 5) * 8;
            float acc[8];
            #pragma unroll
            for (int i = 0; i < 8; i++) acc[i] = sm[OFF_B2 + d0 + i];
            #pragma unroll 4
            for (int c = 0; c < 64; c++) {
                float gv = bufB[c*33 + k];
                const float4* w4 = (const float4*)(sm + OFF_W2 + c*64 + d0);
                float4 w0 = w4[0], w1 = w4[1];
                acc[0] = fmaf(gv, w0.x, acc[0]);
                acc[1] = fmaf(gv, w0.y, acc[1]);
                acc[2] = fmaf(gv, w0.z, acc[2]);
                acc[3] = fmaf(gv, w0.w, acc[3]);
                acc[4] = fmaf(gv, w1.x, acc[4]);
                acc[5] = fmaf(gv, w1.y, acc[5]);
                acc[6] = fmaf(gv, w1.z, acc[6]);
                acc[7] = fmaf(gv, w1.w, acc[7]);
            }
            #pragma unroll
            for (int i = 0; i < 8; i++) bufA[(d0+i)*33 + k] = fmaxf(acc[i], 0.0f);
        }
        __syncthreads();

        // ---- layer 3: [32x64] @ [64x128] -> relu -> warp maxpool -> out ----
        {
            int k = t & 31, d0 = (t >> 5) * 16;
            float acc[16];
            #pragma unroll
            for (int i = 0; i < 16; i++) acc[i] = sm[OFF_B3 + d0 + i];
            #pragma unroll 4
            for (int c = 0; c < 64; c++) {
                float hv = bufA[c*33 + k];
                const float4* w4 = (const float4*)(sm + OFF_W3 + c*128 + d0);
                float4 w0 = w4[0], w1 = w4[1], w2 = w4[2], w3 = w4[3];
                acc[ 0] = fmaf(hv, w0.x, acc[ 0]);
                acc[ 1] = fmaf(hv, w0.y, acc[ 1]);
                acc[ 2] = fmaf(hv, w0.z, acc[ 2]);
                acc[ 3] = fmaf(hv, w0.w, acc[ 3]);
                acc[ 4] = fmaf(hv, w1.x, acc[ 4]);
                acc[ 5] = fmaf(hv, w1.y, acc[ 5]);
                acc[ 6] = fmaf(hv, w1.z, acc[ 6]);
                acc[ 7] = fmaf(hv, w1.w, acc[ 7]);
                acc[ 8] = fmaf(hv, w2.x, acc[ 8]);
                acc[ 9] = fmaf(hv, w2.y, acc[ 9]);
                acc[10] = fmaf(hv, w2.z, acc[10]);
                acc[11] = fmaf(hv, w2.w, acc[11]);
                acc[12] = fmaf(hv, w3.x, acc[12]);
                acc[13] = fmaf(hv, w3.y, acc[13]);
                acc[14] = fmaf(hv, w3.z, acc[14]);
                acc[15] = fmaf(hv, w3.w, acc[15]);
            }
            #pragma unroll
            for (int i = 0; i < 16; i++) {
                float m = fmaxf(acc[i], 0.0f);
                m = fmaxf(m, __shfl_xor_sync(0xffffffffu, m, 16));
                m = fmaxf(m, __shfl_xor_sync(0xffffffffu, m,  8));
                m = fmaxf(m, __shfl_xor_sync(0xffffffffu, m,  4));
                m = fmaxf(m, __shfl_xor_sync(0xffffffffu, m,  2));
                m = fmaxf(m, __shfl_xor_sync(0xffffffffu, m,  1));
                if (lane == 0)
                    out[OFF_FEAT + ((size_t)b * OUTC + d0 + i) * SPTS + s] = m;
            }
        }
        __syncthreads();
    }
}

// ---------------------------------------------------------------------------
extern "C" void kernel_launch(void* const* d_in, const int* in_sizes, int n_in,
                              void* d_out, int out_size) {
    const float* xyz      = (const float*)d_in[0];
    const float* features = (const float*)d_in[1];
    const float* W1 = (const float*)d_in[2];
    const float* b1 = (const float*)d_in[3];
    const float* W2 = (const float*)d_in[4];
    const float* b2 = (const float*)d_in[5];
    const float* W3 = (const float*)d_in[6];
    const float* b3 = (const float*)d_in[7];
    float* out = (float*)d_out;

    // ball query: one warp per centroid
    bq_kernel<<<(BATCH*SPTS*32)/256, 256>>>(xyz);

    // feature transpose [B,C,N] -> [B,N,C]
    {
        dim3 g(NPTS/32, CH/32, BATCH);
        dim3 blk(32, 8);
        transpose_kernel<<<g, blk>>>(features);
    }

    // trivial outputs
    misc_kernel<<<(N_XYZ_OUT + 255)/256, 256>>>(xyz, out);

    // MLP + maxpool
    static bool attr_done = false;
    if (!attr_done) {
        cudaFuncSetAttribute(mlp_kernel, cudaFuncAttributeMaxDynamicSharedMemorySize, SMEM_BYTES);
        attr_done = true;
    }
    mlp_kernel<<<296, MLP_THREADS, SMEM_BYTES>>>(xyz, W1, b1, W2, b2, W3, b3, out);
}